// round 6
// baseline (speedup 1.0000x reference)
#include <cuda_runtime.h>
#include <cuda_bf16.h>
#include <cstdint>

#define EMB_D    256
#define BATCH    128
#define NC       10000
#define NTILE    40                            // 250 * 40 = 10000 exact
#define NBLK     (NC / NTILE)                  // 250 CTAs
#define NTHREADS 256                           // 8 warps

#define TSTRIDE_W 132                          // smem words per row (128 + 4 pad)

// dynamic smem layout (bytes)
#define OFF_LN   0                             // float[128]
#define OFF_TN   512                           // float[40] (padded)
#define OFF_LS   1024                          // left tile 128 x 264 bf16 = 67584 B
#define OFF_TS   (1024 + 67584)                // t tile     40 x 264 bf16 = 21120 B
#define SMEM_DYN (1024 + 67584 + 21120)        // 89728 B

// device-global scratch
__device__ __align__(16) uint4 g_leftT[BATCH * 32];   // bf16-packed left rows
__device__ float g_ln[BATCH];
__device__ __align__(16) uint4 g_tT[NC * 32];         // bf16-packed candidate rows (5.12 MB)
__device__ float g_tn[NC];

// ---------------------------------------------------------------------------
__device__ __forceinline__ void mma_bf16(float* c,
                                         uint32_t a0, uint32_t a1, uint32_t a2, uint32_t a3,
                                         uint32_t b0, uint32_t b1) {
    asm volatile(
        "mma.sync.aligned.m16n8k16.row.col.f32.bf16.bf16.f32 "
        "{%0,%1,%2,%3}, {%4,%5,%6,%7}, {%8,%9}, {%0,%1,%2,%3};"
        : "+f"(c[0]), "+f"(c[1]), "+f"(c[2]), "+f"(c[3])
        : "r"(a0), "r"(a1), "r"(a2), "r"(a3), "r"(b0), "r"(b1));
}

__device__ __forceinline__ uint32_t pack_bf16x2(float lo, float hi) {
    __nv_bfloat162 p = __floats2bfloat162_rn(lo, hi);
    return *reinterpret_cast<uint32_t*>(&p);
}

__device__ __forceinline__ float warp_sum(float s) {
    #pragma unroll
    for (int o = 16; o; o >>= 1) s += __shfl_xor_sync(0xffffffffu, s, o);
    return s;
}

__device__ __forceinline__ void cp_async16(uint32_t smem_dst, const void* gsrc) {
    asm volatile("cp.async.ca.shared.global [%0], [%1], 16;"
                 :: "r"(smem_dst), "l"(gsrc) : "memory");
}

__device__ __forceinline__ uint32_t cvta_smem(const void* p) {
    uint32_t a;
    asm("{ .reg .u64 t; cvta.to.shared.u64 t, %1; cvt.u32.u64 %0, t; }"
        : "=r"(a) : "l"(p));
    return a;
}

// ---------------------------------------------------------------------------
// Kernel 1 (fused pack): dense bf16 candidate matrix + norms; CTAs 0..15 also
// build left = ent[heads]+rel[rels].
// ---------------------------------------------------------------------------
__global__ void __launch_bounds__(NTHREADS)
pack_kernel(const float* __restrict__ ent, const float* __restrict__ rel,
            const int* __restrict__ heads, const int* __restrict__ rels,
            const int* __restrict__ tails) {
    const int wid  = threadIdx.x >> 5;
    const int lane = threadIdx.x & 31;

    // ---- pack 5 tail rows per warp (dense output) ----
    {
        const int nb = blockIdx.x * NTILE + wid * 5;
        int idx[5];
        #pragma unroll
        for (int u = 0; u < 5; u++) idx[u] = tails[nb + u];
        float4 va[5], vb[5];
        #pragma unroll
        for (int u = 0; u < 5; u++) {
            const float4* src = reinterpret_cast<const float4*>(ent + (size_t)idx[u] * EMB_D);
            va[u] = src[lane * 2];
            vb[u] = src[lane * 2 + 1];
        }
        #pragma unroll
        for (int u = 0; u < 5; u++) {
            const int n = nb + u;
            float s = va[u].x*va[u].x + va[u].y*va[u].y + va[u].z*va[u].z + va[u].w*va[u].w
                    + vb[u].x*vb[u].x + vb[u].y*vb[u].y + vb[u].z*vb[u].z + vb[u].w*vb[u].w;
            s = warp_sum(s);
            if (lane == 0) g_tn[n] = s;
            uint4 pk;
            pk.x = pack_bf16x2(va[u].x, va[u].y);
            pk.y = pack_bf16x2(va[u].z, va[u].w);
            pk.z = pack_bf16x2(vb[u].x, vb[u].y);
            pk.w = pack_bf16x2(vb[u].z, vb[u].w);
            g_tT[n * 32 + lane] = pk;
        }
    }

    // ---- CTAs 0..15: build left rows (8 per CTA, one per warp) ----
    if (blockIdx.x < 16) {
        const int r  = blockIdx.x * 8 + wid;
        const int h  = heads[r];
        const int rl = rels[r];
        const float4* eh = reinterpret_cast<const float4*>(ent + (size_t)h * EMB_D);
        const float4* rr = reinterpret_cast<const float4*>(rel + (size_t)rl * EMB_D);
        float4 a0 = eh[lane * 2], a1 = eh[lane * 2 + 1];
        float4 b0 = rr[lane * 2], b1 = rr[lane * 2 + 1];
        float v0 = a0.x + b0.x, v1 = a0.y + b0.y, v2 = a0.z + b0.z, v3 = a0.w + b0.w;
        float v4 = a1.x + b1.x, v5 = a1.y + b1.y, v6 = a1.z + b1.z, v7 = a1.w + b1.w;
        float s = v0*v0 + v1*v1 + v2*v2 + v3*v3 + v4*v4 + v5*v5 + v6*v6 + v7*v7;
        s = warp_sum(s);
        if (lane == 0) g_ln[r] = s;
        uint4 pk;
        pk.x = pack_bf16x2(v0, v1);
        pk.y = pack_bf16x2(v2, v3);
        pk.z = pack_bf16x2(v4, v5);
        pk.w = pack_bf16x2(v6, v7);
        g_leftT[r * 32 + lane] = pk;
    }
}

// ---------------------------------------------------------------------------
// Kernel 2: dense score. Tile = 128 batch x 40 tails, cp.async staging,
// 8 warps (warp tile 16x40), 2 CTAs/SM.
// ---------------------------------------------------------------------------
__global__ void __launch_bounds__(NTHREADS, 2)
score_kernel(float* __restrict__ out) {
    extern __shared__ __align__(16) char smem[];
    float*    ln_s = reinterpret_cast<float*>(smem + OFF_LN);
    float*    tn_s = reinterpret_cast<float*>(smem + OFF_TN);
    uint32_t* lS   = reinterpret_cast<uint32_t*>(smem + OFF_LS);
    uint32_t* tS   = reinterpret_cast<uint32_t*>(smem + OFF_TS);

    const uint32_t lS_a = cvta_smem(lS);
    const uint32_t tS_a = cvta_smem(tS);

    const int tid  = threadIdx.x;
    const int wid  = tid >> 5;
    const int lane = tid & 31;
    const int n0   = blockIdx.x * NTILE;

    // ---- stage t tile via cp.async (dense, contiguous) ----
    #pragma unroll
    for (int it = 0; it < 5; it++) {
        const int u   = it * NTHREADS + tid;     // 1280 uint4
        const int row = u >> 5;
        const int c   = u & 31;
        cp_async16(tS_a + (uint32_t)(row * TSTRIDE_W + c * 4) * 4u,
                   &g_tT[(size_t)(n0 + row) * 32 + c]);
    }
    // ---- stage left tile via cp.async ----
    #pragma unroll
    for (int it = 0; it < 16; it++) {
        const int u   = it * NTHREADS + tid;     // 4096 uint4
        const int row = u >> 5;
        const int c   = u & 31;
        cp_async16(lS_a + (uint32_t)(row * TSTRIDE_W + c * 4) * 4u,
                   &g_leftT[u]);
    }
    asm volatile("cp.async.commit_group;" ::: "memory");

    // norms via regular loads (overlap with cp.async)
    if (tid < BATCH) ln_s[tid] = g_ln[tid];
    if (tid < NTILE) tn_s[tid] = g_tn[n0 + tid];

    asm volatile("cp.async.wait_group 0;" ::: "memory");
    __syncthreads();

    // ---- HMMA mainloop: warp tile 16(batch) x 40(tails) ----
    const int m0  = wid * 16;
    const int g   = lane >> 2;
    const int tig = lane & 3;

    float acc[5][4];
    #pragma unroll
    for (int nb = 0; nb < 5; nb++)
        #pragma unroll
        for (int c = 0; c < 4; c++) acc[nb][c] = 0.0f;

    const int rA0 = (m0 + g) * TSTRIDE_W;
    const int rA1 = (m0 + 8 + g) * TSTRIDE_W;

    #pragma unroll 4
    for (int ks = 0; ks < 16; ks++) {
        const int kw = ks * 8 + tig;

        uint32_t a0 = lS[rA0 + kw];
        uint32_t a1 = lS[rA1 + kw];
        uint32_t a2 = lS[rA0 + kw + 4];
        uint32_t a3 = lS[rA1 + kw + 4];

        uint32_t bb[5][2];
        #pragma unroll
        for (int nb = 0; nb < 5; nb++) {
            const int rB = (nb * 8 + g) * TSTRIDE_W;
            bb[nb][0] = tS[rB + kw];
            bb[nb][1] = tS[rB + kw + 4];
        }
        #pragma unroll
        for (int nb = 0; nb < 5; nb++)
            mma_bf16(acc[nb], a0, a1, a2, a3, bb[nb][0], bb[nb][1]);
    }

    // ---- epilogue: -sqrt(ln + tn - 2*dot) ----
    const int b0r = m0 + g;
    const float l0 = ln_s[b0r];
    const float l1 = ln_s[b0r + 8];

    #pragma unroll
    for (int nb = 0; nb < 5; nb++) {
        const int col = nb * 8 + tig * 2;
        const int n   = n0 + col;
        const float t0 = tn_s[col];
        const float t1 = tn_s[col + 1];
        float v, sq;
        float2 w0, w1;

        v = fmaxf(l0 + t0 - 2.0f * acc[nb][0], 0.0f);
        asm("sqrt.approx.f32 %0, %1;" : "=f"(sq) : "f"(v));  w0.x = -sq;
        v = fmaxf(l0 + t1 - 2.0f * acc[nb][1], 0.0f);
        asm("sqrt.approx.f32 %0, %1;" : "=f"(sq) : "f"(v));  w0.y = -sq;
        v = fmaxf(l1 + t0 - 2.0f * acc[nb][2], 0.0f);
        asm("sqrt.approx.f32 %0, %1;" : "=f"(sq) : "f"(v));  w1.x = -sq;
        v = fmaxf(l1 + t1 - 2.0f * acc[nb][3], 0.0f);
        asm("sqrt.approx.f32 %0, %1;" : "=f"(sq) : "f"(v));  w1.y = -sq;

        *reinterpret_cast<float2*>(out + (size_t)b0r * NC + n)       = w0;
        *reinterpret_cast<float2*>(out + (size_t)(b0r + 8) * NC + n) = w1;
    }
}

// ---------------------------------------------------------------------------
extern "C" void kernel_launch(void* const* d_in, const int* in_sizes, int n_in,
                              void* d_out, int out_size) {
    const float* ent   = (const float*)d_in[0];
    const float* rel   = (const float*)d_in[1];
    const int*   heads = (const int*)d_in[2];
    const int*   rels  = (const int*)d_in[3];
    const int*   tails = (const int*)d_in[4];
    float* out = (float*)d_out;

    cudaFuncSetAttribute(score_kernel,
                         cudaFuncAttributeMaxDynamicSharedMemorySize, SMEM_DYN);

    pack_kernel<<<NBLK, NTHREADS>>>(ent, rel, heads, rels, tails);
    score_kernel<<<NBLK, NTHREADS, SMEM_DYN>>>(out);
}

// round 7
// speedup vs baseline: 1.0025x; 1.0025x over previous
#include <cuda_runtime.h>
#include <cuda_bf16.h>
#include <cstdint>

#define EMB_D    256
#define BATCH    128
#define NC       10000
#define NTILE    80                     // tails per n-tile; 125 * 80 = 10000
#define BHALF    64                     // batch rows per CTA
#define NBLK_S   250                    // 125 n-tiles x 2 batch halves
#define NTHREADS 256

// smem: left 64 rows x 512B = 32768, t 80 rows x 512B = 40960  -> 73728 (72KB)
#define OFF_TS_B 32768
#define SMEM_DYN 73728

// device-global scratch
__device__ __align__(16) uint4 g_leftT[BATCH * 32];
__device__ float g_ln[BATCH];
__device__ __align__(16) uint4 g_tT[NC * 32];
__device__ float g_tn[NC];

// ---------------------------------------------------------------------------
__device__ __forceinline__ void mma_bf16(float* c,
                                         uint32_t a0, uint32_t a1, uint32_t a2, uint32_t a3,
                                         uint32_t b0, uint32_t b1) {
    asm volatile(
        "mma.sync.aligned.m16n8k16.row.col.f32.bf16.bf16.f32 "
        "{%0,%1,%2,%3}, {%4,%5,%6,%7}, {%8,%9}, {%0,%1,%2,%3};"
        : "+f"(c[0]), "+f"(c[1]), "+f"(c[2]), "+f"(c[3])
        : "r"(a0), "r"(a1), "r"(a2), "r"(a3), "r"(b0), "r"(b1));
}

__device__ __forceinline__ uint32_t pack_bf16x2(float lo, float hi) {
    __nv_bfloat162 p = __floats2bfloat162_rn(lo, hi);
    return *reinterpret_cast<uint32_t*>(&p);
}

__device__ __forceinline__ float warp_sum(float s) {
    #pragma unroll
    for (int o = 16; o; o >>= 1) s += __shfl_xor_sync(0xffffffffu, s, o);
    return s;
}

__device__ __forceinline__ void cp_async16(uint32_t smem_dst, const void* gsrc) {
    asm volatile("cp.async.ca.shared.global [%0], [%1], 16;"
                 :: "r"(smem_dst), "l"(gsrc) : "memory");
}

__device__ __forceinline__ uint32_t cvta_smem(const void* p) {
    uint32_t a;
    asm("{ .reg .u64 t; cvta.to.shared.u64 t, %1; cvt.u32.u64 %0, t; }"
        : "=r"(a) : "l"(p));
    return a;
}

// ---------------------------------------------------------------------------
// Kernel 1: pack dense bf16 candidate matrix + norms (2 rows per warp,
// 625 CTAs for max outstanding gathers); CTAs 0..15 also build left.
// ---------------------------------------------------------------------------
__global__ void __launch_bounds__(NTHREADS)
pack_kernel(const float* __restrict__ ent, const float* __restrict__ rel,
            const int* __restrict__ heads, const int* __restrict__ rels,
            const int* __restrict__ tails) {
    const int wid  = threadIdx.x >> 5;
    const int lane = threadIdx.x & 31;

    // ---- pack 2 tail rows per warp ----
    {
        const int nb = blockIdx.x * 16 + wid * 2;
        int i0 = tails[nb], i1 = tails[nb + 1];
        const float4* s0 = reinterpret_cast<const float4*>(ent + (size_t)i0 * EMB_D);
        const float4* s1 = reinterpret_cast<const float4*>(ent + (size_t)i1 * EMB_D);
        float4 a0 = s0[lane * 2], b0 = s0[lane * 2 + 1];
        float4 a1 = s1[lane * 2], b1 = s1[lane * 2 + 1];

        float n0 = a0.x*a0.x + a0.y*a0.y + a0.z*a0.z + a0.w*a0.w
                 + b0.x*b0.x + b0.y*b0.y + b0.z*b0.z + b0.w*b0.w;
        float n1 = a1.x*a1.x + a1.y*a1.y + a1.z*a1.z + a1.w*a1.w
                 + b1.x*b1.x + b1.y*b1.y + b1.z*b1.z + b1.w*b1.w;
        n0 = warp_sum(n0);
        n1 = warp_sum(n1);
        if (lane == 0) { g_tn[nb] = n0; g_tn[nb + 1] = n1; }

        uint4 p0, p1;
        p0.x = pack_bf16x2(a0.x, a0.y); p0.y = pack_bf16x2(a0.z, a0.w);
        p0.z = pack_bf16x2(b0.x, b0.y); p0.w = pack_bf16x2(b0.z, b0.w);
        p1.x = pack_bf16x2(a1.x, a1.y); p1.y = pack_bf16x2(a1.z, a1.w);
        p1.z = pack_bf16x2(b1.x, b1.y); p1.w = pack_bf16x2(b1.z, b1.w);
        g_tT[(size_t)nb * 32 + lane]       = p0;
        g_tT[(size_t)(nb + 1) * 32 + lane] = p1;
    }

    // ---- CTAs 0..15: build left rows (one per warp) ----
    if (blockIdx.x < 16) {
        const int r  = blockIdx.x * 8 + wid;
        const int h  = heads[r];
        const int rl = rels[r];
        const float4* eh = reinterpret_cast<const float4*>(ent + (size_t)h * EMB_D);
        const float4* rr = reinterpret_cast<const float4*>(rel + (size_t)rl * EMB_D);
        float4 a0 = eh[lane * 2], a1 = eh[lane * 2 + 1];
        float4 b0 = rr[lane * 2], b1 = rr[lane * 2 + 1];
        float v0 = a0.x + b0.x, v1 = a0.y + b0.y, v2 = a0.z + b0.z, v3 = a0.w + b0.w;
        float v4 = a1.x + b1.x, v5 = a1.y + b1.y, v6 = a1.z + b1.z, v7 = a1.w + b1.w;
        float s = v0*v0 + v1*v1 + v2*v2 + v3*v3 + v4*v4 + v5*v5 + v6*v6 + v7*v7;
        s = warp_sum(s);
        if (lane == 0) g_ln[r] = s;
        uint4 pk;
        pk.x = pack_bf16x2(v0, v1);
        pk.y = pack_bf16x2(v2, v3);
        pk.z = pack_bf16x2(v4, v5);
        pk.w = pack_bf16x2(v6, v7);
        g_leftT[r * 32 + lane] = pk;
    }
}

// ---------------------------------------------------------------------------
// Kernel 2: score. Tile = 64 batch x 80 tails, XOR-swizzled smem (72KB),
// 3 CTAs/SM, 8 warps (m: 4 x 16, n: 2 x 40).
// ---------------------------------------------------------------------------
__global__ void __launch_bounds__(NTHREADS, 3)
score_kernel(float* __restrict__ out) {
    extern __shared__ __align__(16) char smem[];
    uint32_t* lS = reinterpret_cast<uint32_t*>(smem);
    uint32_t* tS = reinterpret_cast<uint32_t*>(smem + OFF_TS_B);
    const uint32_t lS_a = cvta_smem(lS);
    const uint32_t tS_a = cvta_smem(tS);

    const int tid  = threadIdx.x;
    const int wid  = tid >> 5;
    const int lane = tid & 31;
    const int n0   = (blockIdx.x >> 1) * NTILE;
    const int half = blockIdx.x & 1;

    // ---- stage left (64 rows, 2048 uint4) with XOR swizzle ----
    #pragma unroll
    for (int it = 0; it < 8; it++) {
        const int i   = it * NTHREADS + tid;
        const int row = i >> 5;
        const int u   = i & 31;
        const uint32_t w = (uint32_t)(row * 128 + ((u ^ (row & 7)) << 2));
        cp_async16(lS_a + w * 4u, &g_leftT[(half * BHALF + row) * 32 + u]);
    }
    // ---- stage t (80 rows, 2560 uint4) ----
    #pragma unroll
    for (int it = 0; it < 10; it++) {
        const int i   = it * NTHREADS + tid;
        const int row = i >> 5;
        const int u   = i & 31;
        const uint32_t w = (uint32_t)(row * 128 + ((u ^ (row & 7)) << 2));
        cp_async16(tS_a + w * 4u, &g_tT[(size_t)(n0 + row) * 32 + u]);
    }
    asm volatile("cp.async.commit_group;" ::: "memory");

    // ---- norms into registers (L2-hot, overlaps cp.async) ----
    const int m0  = (wid & 3) * 16;
    const int nw0 = (wid >> 2) * 40;
    const int g   = lane >> 2;
    const int tig = lane & 3;

    const int bgl = half * BHALF + m0 + g;
    const float l0 = g_ln[bgl];
    const float l1 = g_ln[bgl + 8];
    float t0r[5], t1r[5];
    #pragma unroll
    for (int nb = 0; nb < 5; nb++) {
        const int col = nw0 + nb * 8 + tig * 2;
        t0r[nb] = g_tn[n0 + col];
        t1r[nb] = g_tn[n0 + col + 1];
    }

    asm volatile("cp.async.wait_group 0;" ::: "memory");
    __syncthreads();

    // ---- HMMA mainloop ----
    float acc[5][4];
    #pragma unroll
    for (int nb = 0; nb < 5; nb++)
        #pragma unroll
        for (int c = 0; c < 4; c++) acc[nb][c] = 0.0f;

    const int baseA = (m0 + g) * 128 + tig;
    int baseB[5];
    #pragma unroll
    for (int nb = 0; nb < 5; nb++) baseB[nb] = (nw0 + nb * 8 + g) * 128 + tig;

    #pragma unroll 4
    for (int ks = 0; ks < 16; ks++) {
        const int e0 = (2 * ks) ^ g;
        const int o0 = e0 << 2;
        const int o1 = (e0 ^ 1) << 2;

        uint32_t a0 = lS[baseA + o0];
        uint32_t a1 = lS[baseA + 1024 + o0];
        uint32_t a2 = lS[baseA + o1];
        uint32_t a3 = lS[baseA + 1024 + o1];

        uint32_t bb[5][2];
        #pragma unroll
        for (int nb = 0; nb < 5; nb++) {
            bb[nb][0] = tS[baseB[nb] + o0];
            bb[nb][1] = tS[baseB[nb] + o1];
        }
        #pragma unroll
        for (int nb = 0; nb < 5; nb++)
            mma_bf16(acc[nb], a0, a1, a2, a3, bb[nb][0], bb[nb][1]);
    }

    // ---- epilogue ----
    #pragma unroll
    for (int nb = 0; nb < 5; nb++) {
        const int n = n0 + nw0 + nb * 8 + tig * 2;
        float v, sq;
        float2 w0, w1;
        v = fmaxf(l0 + t0r[nb] - 2.0f * acc[nb][0], 0.0f);
        asm("sqrt.approx.f32 %0, %1;" : "=f"(sq) : "f"(v));  w0.x = -sq;
        v = fmaxf(l0 + t1r[nb] - 2.0f * acc[nb][1], 0.0f);
        asm("sqrt.approx.f32 %0, %1;" : "=f"(sq) : "f"(v));  w0.y = -sq;
        v = fmaxf(l1 + t0r[nb] - 2.0f * acc[nb][2], 0.0f);
        asm("sqrt.approx.f32 %0, %1;" : "=f"(sq) : "f"(v));  w1.x = -sq;
        v = fmaxf(l1 + t1r[nb] - 2.0f * acc[nb][3], 0.0f);
        asm("sqrt.approx.f32 %0, %1;" : "=f"(sq) : "f"(v));  w1.y = -sq;

        *reinterpret_cast<float2*>(out + (size_t)bgl * NC + n)       = w0;
        *reinterpret_cast<float2*>(out + (size_t)(bgl + 8) * NC + n) = w1;
    }
}

// ---------------------------------------------------------------------------
extern "C" void kernel_launch(void* const* d_in, const int* in_sizes, int n_in,
                              void* d_out, int out_size) {
    const float* ent   = (const float*)d_in[0];
    const float* rel   = (const float*)d_in[1];
    const int*   heads = (const int*)d_in[2];
    const int*   rels  = (const int*)d_in[3];
    const int*   tails = (const int*)d_in[4];
    float* out = (float*)d_out;

    cudaFuncSetAttribute(score_kernel,
                         cudaFuncAttributeMaxDynamicSharedMemorySize, SMEM_DYN);

    pack_kernel<<<NC / 16, NTHREADS>>>(ent, rel, heads, rels, tails);
    score_kernel<<<NBLK_S, NTHREADS, SMEM_DYN>>>(out);
}